// round 7
// baseline (speedup 1.0000x reference)
#include <cuda_runtime.h>
#include <cuda_fp16.h>
#include <cstdint>

#define D 64
#define MAXNTOT 340008
#define MAXNNZALL 4000008
#define SCAN_B 256
#define MAXBLKSA ((MAXNTOT + SCAN_B - 1) / SCAN_B)

// ---- scratch (__device__ globals; no allocation allowed) ----
__device__ __align__(16) __half g_f0[(size_t)MAXNTOT * D];   // ~43.5 MB
__device__ __align__(16) __half g_f1[(size_t)MAXNTOT * D];   // ~43.5 MB
__device__ __align__(16) float2 g_edges[MAXNNZALL];          // {global col bits, val}
__device__ int g_counts[MAXNTOT];
__device__ int g_offs[MAXNTOT + 1];
__device__ int g_cursor[MAXNTOT];
__device__ unsigned long long g_desc[MAXBLKSA];
__device__ unsigned int g_ticket;

// ---- init: f0(fp16) = concat of all three propagation inputs ----
__global__ void init_kernel(const float* __restrict__ Uf, const float* __restrict__ If,
                            const float* __restrict__ Bf,
                            int U, int NB, int R1, int R2, int ntot,
                            __half* __restrict__ f0) {
    int idx = blockIdx.x * blockDim.x + threadIdx.x;
    if (idx >= ntot * (D / 4)) return;
    int row = idx >> 4;
    int c = (idx & 15) * 4;
    const float* src;
    if (row < R1) {
        src = (row < U) ? (Uf + (size_t)row * D) : (If + (size_t)(row - U) * D);
    } else if (row < R2) {
        int l = row - R1;
        src = (l < NB) ? (Bf + (size_t)l * D) : (If + (size_t)(l - NB) * D);
    } else {
        int l = row - R2;
        src = (l < U) ? (Uf + (size_t)l * D) : (Bf + (size_t)(l - U) * D);
    }
    float4 v = *(const float4*)(src + c);
    __half2 h0 = __floats2half2_rn(v.x, v.y);
    __half2 h1 = __floats2half2_rn(v.z, v.w);
    uint2 packed;
    packed.x = *(const unsigned int*)&h0;
    packed.y = *(const unsigned int*)&h1;
    *(uint2*)(f0 + (size_t)row * D + c) = packed;
}

// ---- merged histogram over all 3 edge lists (global row ids) ----
__global__ void hist_kernel(const int* __restrict__ r0, const int* __restrict__ r1,
                            const int* __restrict__ r2,
                            int n0, int n1, int n2, int R1, int R2,
                            int* __restrict__ counts) {
    int base = (blockIdx.x * blockDim.x + threadIdx.x) * 4;
    int ntote = n0 + n1 + n2;
    if (base >= ntote) return;
    if (base + 4 <= n0) {
        int4 r = *(const int4*)(r0 + base);
        atomicAdd(&counts[r.x], 1); atomicAdd(&counts[r.y], 1);
        atomicAdd(&counts[r.z], 1); atomicAdd(&counts[r.w], 1);
    } else if (base >= n0 && base + 4 <= n0 + n1) {
        int4 r = *(const int4*)(r1 + (base - n0));
        atomicAdd(&counts[r.x + R1], 1); atomicAdd(&counts[r.y + R1], 1);
        atomicAdd(&counts[r.z + R1], 1); atomicAdd(&counts[r.w + R1], 1);
    } else if (base >= n0 + n1 && base + 4 <= ntote) {
        int4 r = *(const int4*)(r2 + (base - n0 - n1));
        atomicAdd(&counts[r.x + R2], 1); atomicAdd(&counts[r.y + R2], 1);
        atomicAdd(&counts[r.z + R2], 1); atomicAdd(&counts[r.w + R2], 1);
    } else {
        int end = min(base + 4, ntote);
        for (int k = base; k < end; k++) {
            int row;
            if (k < n0) row = r0[k];
            else if (k < n0 + n1) row = r1[k - n0] + R1;
            else row = r2[k - n0 - n1] + R2;
            atomicAdd(&counts[row], 1);
        }
    }
}

// ---- single-pass decoupled-lookback exclusive scan -> offs + cursor ----
__global__ void scan_kernel(const int* __restrict__ counts, int n,
                            int* __restrict__ offs, int* __restrict__ cursor,
                            unsigned long long* __restrict__ desc,
                            unsigned int* __restrict__ ticket) {
    __shared__ int s_warp[8];
    __shared__ int s_bid;
    __shared__ int s_excl;
    int lane = threadIdx.x & 31;
    int wid = threadIdx.x >> 5;
    if (threadIdx.x == 0) s_bid = (int)atomicAdd(ticket, 1u);
    __syncthreads();
    int bid = s_bid;
    int i = bid * SCAN_B + threadIdx.x;
    int v = (i < n) ? counts[i] : 0;
    int x = v;
    #pragma unroll
    for (int o = 1; o < 32; o <<= 1) {
        int t = __shfl_up_sync(0xffffffffu, x, o);
        if (lane >= o) x += t;
    }
    if (lane == 31) s_warp[wid] = x;
    __syncthreads();
    if (wid == 0 && lane < 8) {
        int w = s_warp[lane];
        #pragma unroll
        for (int o = 1; o < 8; o <<= 1) {
            int t = __shfl_up_sync(0xffu, w, o);
            if (lane >= o) w += t;
        }
        s_warp[lane] = w;
    }
    __syncthreads();
    int incl = x + (wid ? s_warp[wid - 1] : 0);
    int total = s_warp[7];
    if (threadIdx.x == 0) {
        if (bid == 0) {
            atomicExch(&desc[0], (2ULL << 62) | (unsigned long long)(unsigned)total);
            s_excl = 0;
        } else {
            atomicExch(&desc[bid], (1ULL << 62) | (unsigned long long)(unsigned)total);
            int excl = 0;
            int j = bid - 1;
            while (true) {
                unsigned long long d;
                do { d = atomicAdd(&desc[j], 0ULL); } while ((d >> 62) == 0ULL);
                excl += (int)(unsigned)d;
                if ((d >> 62) == 2ULL) break;
                j--;
            }
            s_excl = excl;
            atomicExch(&desc[bid], (2ULL << 62) | (unsigned long long)(unsigned)(excl + total));
        }
    }
    __syncthreads();
    int excl = s_excl;
    if (i < n) {
        int inc = incl + excl;
        offs[i + 1] = inc;
        cursor[i] = inc - v;
        if (i == 0) offs[0] = 0;
    }
}

// ---- merged bucket: all edges -> (global col, val), grouped by global row ----
__global__ void bucket_kernel(const int* __restrict__ r0, const int* __restrict__ c0,
                              const float* __restrict__ v0,
                              const int* __restrict__ r1, const int* __restrict__ c1,
                              const float* __restrict__ v1,
                              const int* __restrict__ r2, const int* __restrict__ c2,
                              const float* __restrict__ v2,
                              int n0, int n1, int n2, int R1, int R2,
                              int* __restrict__ cursor, float2* __restrict__ edges) {
    int base = (blockIdx.x * blockDim.x + threadIdx.x) * 4;
    int ntote = n0 + n1 + n2;
    if (base >= ntote) return;
    if (base + 4 <= n0) {
        int4 r = *(const int4*)(r0 + base);
        int4 c = *(const int4*)(c0 + base);
        float4 v = *(const float4*)(v0 + base);
        int p0 = atomicAdd(&cursor[r.x], 1);
        int p1 = atomicAdd(&cursor[r.y], 1);
        int p2 = atomicAdd(&cursor[r.z], 1);
        int p3 = atomicAdd(&cursor[r.w], 1);
        edges[p0] = make_float2(__int_as_float(c.x), v.x);
        edges[p1] = make_float2(__int_as_float(c.y), v.y);
        edges[p2] = make_float2(__int_as_float(c.z), v.z);
        edges[p3] = make_float2(__int_as_float(c.w), v.w);
    } else if (base >= n0 && base + 4 <= n0 + n1) {
        int b = base - n0;
        int4 r = *(const int4*)(r1 + b);
        int4 c = *(const int4*)(c1 + b);
        float4 v = *(const float4*)(v1 + b);
        int p0 = atomicAdd(&cursor[r.x + R1], 1);
        int p1 = atomicAdd(&cursor[r.y + R1], 1);
        int p2 = atomicAdd(&cursor[r.z + R1], 1);
        int p3 = atomicAdd(&cursor[r.w + R1], 1);
        edges[p0] = make_float2(__int_as_float(c.x + R1), v.x);
        edges[p1] = make_float2(__int_as_float(c.y + R1), v.y);
        edges[p2] = make_float2(__int_as_float(c.z + R1), v.z);
        edges[p3] = make_float2(__int_as_float(c.w + R1), v.w);
    } else if (base >= n0 + n1 && base + 4 <= ntote) {
        int b = base - n0 - n1;
        int4 r = *(const int4*)(r2 + b);
        int4 c = *(const int4*)(c2 + b);
        float4 v = *(const float4*)(v2 + b);
        int p0 = atomicAdd(&cursor[r.x + R2], 1);
        int p1 = atomicAdd(&cursor[r.y + R2], 1);
        int p2 = atomicAdd(&cursor[r.z + R2], 1);
        int p3 = atomicAdd(&cursor[r.w + R2], 1);
        edges[p0] = make_float2(__int_as_float(c.x + R2), v.x);
        edges[p1] = make_float2(__int_as_float(c.y + R2), v.y);
        edges[p2] = make_float2(__int_as_float(c.z + R2), v.z);
        edges[p3] = make_float2(__int_as_float(c.w + R2), v.w);
    } else {
        int end = min(base + 4, ntote);
        for (int k = base; k < end; k++) {
            int row, col; float val;
            if (k < n0) { row = r0[k]; col = c0[k]; val = v0[k]; }
            else if (k < n0 + n1) { int b = k - n0; row = r1[b] + R1; col = c1[b] + R1; val = v1[b]; }
            else { int b = k - n0 - n1; row = r2[b] + R2; col = c2[b] + R2; val = v2[b]; }
            int pos = atomicAdd(&cursor[row], 1);
            edges[pos] = make_float2(__int_as_float(col), val);
        }
    }
}

// map global row -> output row pointer (fixed packing of the 6 tables)
__device__ __forceinline__ float* out_ptr(float* out, int row, int U, int NI, int NB,
                                          int R1, int R2) {
    size_t off;
    if (row < R1) {                   // UI: users | items
        off = (row < U) ? (size_t)row
                        : (size_t)(2 * U + 2 * NB) + (row - U);
    } else if (row < R2) {            // BI: bundles | items
        int l = row - R1;
        off = (l < NB) ? (size_t)(2 * U) + l
                       : (size_t)(2 * U + 2 * NB + NI) + (l - NB);
    } else {                          // UB: users | bundles
        int l = row - R2;
        off = (l < U) ? (size_t)U + l
                      : (size_t)(2 * U + NB) + (l - U);
    }
    return out + off * D;
}

// ---- fused gather-SpMM (fp16 feats, fp32 accum) + L2 norm + output, all rows ----
template <bool FIRST>
__global__ void spmm_kernel(const float2* __restrict__ edges, const int* __restrict__ offs,
                            const __half* __restrict__ fin, __half* __restrict__ fnext,
                            int ntot, int U, int NI, int NB, int R1, int R2,
                            float* __restrict__ out) {
    int row = (int)((blockIdx.x * blockDim.x + threadIdx.x) >> 5);
    if (row >= ntot) return;
    int lane = threadIdx.x & 31;
    int chunk = lane & 15;
    int half = lane >> 4;
    int s = offs[row], e = offs[row + 1];
    int mid = s + (((e - s) + 1) >> 1);
    int lo = half ? mid : s;
    int hi = half ? e : mid;

    float4 acc0 = make_float4(0.f, 0.f, 0.f, 0.f);
    float4 acc1 = acc0;
    int i = lo;
    for (; i + 4 <= hi; i += 4) {
        float2 e0 = __ldg(edges + i);
        float2 e1 = __ldg(edges + i + 1);
        float2 e2 = __ldg(edges + i + 2);
        float2 e3 = __ldg(edges + i + 3);
        uint2 r0 = *((const uint2*)(fin + (size_t)__float_as_int(e0.x) * D) + chunk);
        uint2 r1 = *((const uint2*)(fin + (size_t)__float_as_int(e1.x) * D) + chunk);
        uint2 r2 = *((const uint2*)(fin + (size_t)__float_as_int(e2.x) * D) + chunk);
        uint2 r3 = *((const uint2*)(fin + (size_t)__float_as_int(e3.x) * D) + chunk);
        float2 a0 = __half22float2(*(__half2*)&r0.x), b0 = __half22float2(*(__half2*)&r0.y);
        float2 a1 = __half22float2(*(__half2*)&r1.x), b1 = __half22float2(*(__half2*)&r1.y);
        float2 a2 = __half22float2(*(__half2*)&r2.x), b2 = __half22float2(*(__half2*)&r2.y);
        float2 a3 = __half22float2(*(__half2*)&r3.x), b3 = __half22float2(*(__half2*)&r3.y);
        acc0.x += e0.y * a0.x; acc0.y += e0.y * a0.y; acc0.z += e0.y * b0.x; acc0.w += e0.y * b0.y;
        acc1.x += e1.y * a1.x; acc1.y += e1.y * a1.y; acc1.z += e1.y * b1.x; acc1.w += e1.y * b1.y;
        acc0.x += e2.y * a2.x; acc0.y += e2.y * a2.y; acc0.z += e2.y * b2.x; acc0.w += e2.y * b2.y;
        acc1.x += e3.y * a3.x; acc1.y += e3.y * a3.y; acc1.z += e3.y * b3.x; acc1.w += e3.y * b3.y;
    }
    for (; i < hi; i++) {
        float2 h = __ldg(edges + i);
        uint2 r = *((const uint2*)(fin + (size_t)__float_as_int(h.x) * D) + chunk);
        float2 a = __half22float2(*(__half2*)&r.x), b = __half22float2(*(__half2*)&r.y);
        acc0.x += h.y * a.x; acc0.y += h.y * a.y; acc0.z += h.y * b.x; acc0.w += h.y * b.y;
    }
    float4 a = make_float4(acc0.x + acc1.x, acc0.y + acc1.y,
                           acc0.z + acc1.z, acc0.w + acc1.w);
    a.x += __shfl_xor_sync(0xffffffffu, a.x, 16);
    a.y += __shfl_xor_sync(0xffffffffu, a.y, 16);
    a.z += __shfl_xor_sync(0xffffffffu, a.z, 16);
    a.w += __shfl_xor_sync(0xffffffffu, a.w, 16);
    float ss = a.x * a.x + a.y * a.y + a.z * a.z + a.w * a.w;
    #pragma unroll
    for (int o = 8; o; o >>= 1) ss += __shfl_xor_sync(0xffffffffu, ss, o);
    const float k = 1.0f / 3.0f;
    float scale = k / fmaxf(sqrtf(ss), 1e-12f);

    float* dst = out_ptr(out, row, U, NI, NB, R1, R2);
    if (FIRST) {
        if (half == 0) {
            __half2 h0 = __floats2half2_rn(a.x, a.y);
            __half2 h1 = __floats2half2_rn(a.z, a.w);
            uint2 packed;
            packed.x = *(const unsigned int*)&h0;
            packed.y = *(const unsigned int*)&h1;
            *((uint2*)(fnext + (size_t)row * D) + chunk) = packed;
        } else {
            uint2 r = *((const uint2*)(fin + (size_t)row * D) + chunk);
            float2 fa = __half22float2(*(__half2*)&r.x);
            float2 fb = __half22float2(*(__half2*)&r.y);
            *((float4*)dst + chunk) = make_float4(
                fa.x * k + a.x * scale, fa.y * k + a.y * scale,
                fb.x * k + a.z * scale, fb.y * k + a.w * scale);
        }
    } else {
        if (half == 0) {
            float4* d = (float4*)dst + chunk;
            float4 o = *d;
            o.x += a.x * scale; o.y += a.y * scale;
            o.z += a.z * scale; o.w += a.w * scale;
            *d = o;
        }
    }
}

// ---- persistent streams/events ----
static cudaStream_t s_strm;
static cudaEvent_t s_root, s_build;
static bool s_ready = false;

extern "C" void kernel_launch(void* const* d_in, const int* in_sizes, int n_in,
                              void* d_out, int out_size) {
    const float* users_feature   = (const float*)d_in[0];
    const float* items_feature   = (const float*)d_in[1];
    const float* bundles_feature = (const float*)d_in[2];
    const float* ui_vals = (const float*)d_in[3];
    const float* bi_vals = (const float*)d_in[4];
    const float* ub_vals = (const float*)d_in[5];
    const int* ui_rows = (const int*)d_in[6];
    const int* ui_cols = (const int*)d_in[7];
    const int* bi_rows = (const int*)d_in[8];
    const int* bi_cols = (const int*)d_in[9];
    const int* ub_rows = (const int*)d_in[10];
    const int* ub_cols = (const int*)d_in[11];

    int U  = in_sizes[0] / D;
    int NI = in_sizes[1] / D;
    int NB = in_sizes[2] / D;
    int n0 = in_sizes[3];
    int n1 = in_sizes[4];
    int n2 = in_sizes[5];

    int R1 = U + NI;
    int R2 = R1 + NB + NI;
    int ntot = R2 + U + NB;
    int ntote = n0 + n1 + n2;

    if (!s_ready) {
        cudaStreamCreateWithFlags(&s_strm, cudaStreamNonBlocking);
        cudaEventCreateWithFlags(&s_root, cudaEventDisableTiming);
        cudaEventCreateWithFlags(&s_build, cudaEventDisableTiming);
        s_ready = true;
    }

    float* out = (float*)d_out;
    __half *f0, *f1;
    float2* edges;
    int *counts, *offs, *cursor;
    unsigned long long* desc;
    unsigned int* ticket;
    cudaGetSymbolAddress((void**)&f0, g_f0);
    cudaGetSymbolAddress((void**)&f1, g_f1);
    cudaGetSymbolAddress((void**)&edges, g_edges);
    cudaGetSymbolAddress((void**)&counts, g_counts);
    cudaGetSymbolAddress((void**)&offs, g_offs);
    cudaGetSymbolAddress((void**)&cursor, g_cursor);
    cudaGetSymbolAddress((void**)&desc, g_desc);
    cudaGetSymbolAddress((void**)&ticket, g_ticket);

    int nb = (ntot + SCAN_B - 1) / SCAN_B;
    int eth = (ntote + 3) / 4;

    // Phase A: CSR build on side stream ∥ f0 init on main stream
    cudaEventRecord(s_root, 0);
    cudaStreamWaitEvent(s_strm, s_root, 0);

    cudaMemsetAsync(counts, 0, (size_t)ntot * sizeof(int), s_strm);
    cudaMemsetAsync(desc, 0, (size_t)nb * sizeof(unsigned long long), s_strm);
    cudaMemsetAsync(ticket, 0, sizeof(unsigned int), s_strm);
    hist_kernel<<<(eth + 255) / 256, 256, 0, s_strm>>>(
        ui_rows, bi_rows, ub_rows, n0, n1, n2, R1, R2, counts);
    scan_kernel<<<nb, SCAN_B, 0, s_strm>>>(counts, ntot, offs, cursor, desc, ticket);
    bucket_kernel<<<(eth + 255) / 256, 256, 0, s_strm>>>(
        ui_rows, ui_cols, ui_vals, bi_rows, bi_cols, bi_vals,
        ub_rows, ub_cols, ub_vals, n0, n1, n2, R1, R2, cursor, edges);
    cudaEventRecord(s_build, s_strm);

    init_kernel<<<(ntot * (D / 4) + 255) / 256, 256>>>(
        users_feature, items_feature, bundles_feature, U, NB, R1, R2, ntot, f0);

    // Phase B/C: single spmm per layer over all rows (L2-resident sets)
    cudaStreamWaitEvent(0, s_build, 0);
    int blocks = (ntot + 7) / 8;
    spmm_kernel<true><<<blocks, 256>>>(edges, offs, f0, f1,
                                       ntot, U, NI, NB, R1, R2, out);
    spmm_kernel<false><<<blocks, 256>>>(edges, offs, f1, nullptr,
                                        ntot, U, NI, NB, R1, R2, out);
}

// round 8
// speedup vs baseline: 1.0804x; 1.0804x over previous
#include <cuda_runtime.h>
#include <cuda_fp16.h>
#include <cstdint>

#define D 64
#define MAXNTOT 340008
#define MAXNNZALL 4000008
#define SCAN_B 256
#define MAXBLKS ((150016 + SCAN_B - 1) / SCAN_B)

// ---- scratch (__device__ globals; no allocation allowed) ----
__device__ __align__(16) __half g_f0[(size_t)MAXNTOT * D];   // ~43.5 MB
__device__ __align__(16) __half g_f1[(size_t)MAXNTOT * D];   // ~43.5 MB
__device__ __align__(16) float2 g_edges[MAXNNZALL];          // {global col bits, val}
__device__ int g_counts[MAXNTOT];
__device__ int g_offs[MAXNTOT + 1];
__device__ int g_cursor[MAXNTOT];
__device__ unsigned long long g_desc[3][MAXBLKS];
__device__ unsigned int g_ticket[3];

// ---- init: f0(fp16) = concat of all three propagation inputs ----
__global__ void init_kernel(const float* __restrict__ Uf, const float* __restrict__ If,
                            const float* __restrict__ Bf,
                            int U, int NB, int R1, int R2, int ntot,
                            __half* __restrict__ f0) {
    int idx = blockIdx.x * blockDim.x + threadIdx.x;
    if (idx >= ntot * (D / 4)) return;
    int row = idx >> 4;
    int c = (idx & 15) * 4;
    const float* src;
    if (row < R1) {
        src = (row < U) ? (Uf + (size_t)row * D) : (If + (size_t)(row - U) * D);
    } else if (row < R2) {
        int l = row - R1;
        src = (l < NB) ? (Bf + (size_t)l * D) : (If + (size_t)(l - NB) * D);
    } else {
        int l = row - R2;
        src = (l < U) ? (Uf + (size_t)l * D) : (Bf + (size_t)(l - U) * D);
    }
    float4 v = *(const float4*)(src + c);
    __half2 h0 = __floats2half2_rn(v.x, v.y);
    __half2 h1 = __floats2half2_rn(v.z, v.w);
    uint2 packed;
    packed.x = *(const unsigned int*)&h0;
    packed.y = *(const unsigned int*)&h1;
    *(uint2*)(f0 + (size_t)row * D + c) = packed;
}

// ---- per-graph histogram (8 edges/thread) ----
__global__ void hist_kernel(const int* __restrict__ rows, int nnz, int* __restrict__ counts) {
    int base = (blockIdx.x * blockDim.x + threadIdx.x) * 8;
    if (base + 8 <= nnz) {
        int4 r0 = *(const int4*)(rows + base);
        int4 r1 = *(const int4*)(rows + base + 4);
        atomicAdd(&counts[r0.x], 1); atomicAdd(&counts[r0.y], 1);
        atomicAdd(&counts[r0.z], 1); atomicAdd(&counts[r0.w], 1);
        atomicAdd(&counts[r1.x], 1); atomicAdd(&counts[r1.y], 1);
        atomicAdd(&counts[r1.z], 1); atomicAdd(&counts[r1.w], 1);
    } else {
        for (int k = base; k < nnz; k++) atomicAdd(&counts[rows[k]], 1);
    }
}

// ---- per-graph decoupled-lookback scan; writes GLOBAL offsets (base = edge base) ----
__global__ void scan_kernel(const int* __restrict__ counts, int n, int base,
                            int* __restrict__ offs, int* __restrict__ cursor,
                            unsigned long long* __restrict__ desc,
                            unsigned int* __restrict__ ticket) {
    __shared__ int s_warp[8];
    __shared__ int s_bid;
    __shared__ int s_excl;
    int lane = threadIdx.x & 31;
    int wid = threadIdx.x >> 5;
    if (threadIdx.x == 0) s_bid = (int)atomicAdd(ticket, 1u);
    __syncthreads();
    int bid = s_bid;
    int i = bid * SCAN_B + threadIdx.x;
    int v = (i < n) ? counts[i] : 0;
    int x = v;
    #pragma unroll
    for (int o = 1; o < 32; o <<= 1) {
        int t = __shfl_up_sync(0xffffffffu, x, o);
        if (lane >= o) x += t;
    }
    if (lane == 31) s_warp[wid] = x;
    __syncthreads();
    if (wid == 0 && lane < 8) {
        int w = s_warp[lane];
        #pragma unroll
        for (int o = 1; o < 8; o <<= 1) {
            int t = __shfl_up_sync(0xffu, w, o);
            if (lane >= o) w += t;
        }
        s_warp[lane] = w;
    }
    __syncthreads();
    int incl = x + (wid ? s_warp[wid - 1] : 0);
    int total = s_warp[7];
    if (threadIdx.x == 0) {
        if (bid == 0) {
            atomicExch(&desc[0], (2ULL << 62) | (unsigned long long)(unsigned)total);
            s_excl = 0;
        } else {
            atomicExch(&desc[bid], (1ULL << 62) | (unsigned long long)(unsigned)total);
            int excl = 0;
            int j = bid - 1;
            while (true) {
                unsigned long long d;
                do { d = atomicAdd(&desc[j], 0ULL); } while ((d >> 62) == 0ULL);
                excl += (int)(unsigned)d;
                if ((d >> 62) == 2ULL) break;
                j--;
            }
            s_excl = excl;
            atomicExch(&desc[bid], (2ULL << 62) | (unsigned long long)(unsigned)(excl + total));
        }
    }
    __syncthreads();
    int excl = s_excl;
    if (i < n) {
        int inc = incl + excl + base;
        offs[i + 1] = inc;
        cursor[i] = inc - v;
        if (i == 0) offs[0] = base;
    }
}

// ---- per-graph bucket: edges -> (GLOBAL col = local + cbase, val) ----
__global__ void bucket_kernel(const int* __restrict__ rows, const int* __restrict__ cols,
                              const float* __restrict__ vals, int nnz, int cbase,
                              int* __restrict__ cursor, float2* __restrict__ edges) {
    int base = (blockIdx.x * blockDim.x + threadIdx.x) * 8;
    if (base + 8 <= nnz) {
        int4 ra = *(const int4*)(rows + base);
        int4 rb = *(const int4*)(rows + base + 4);
        int4 ca = *(const int4*)(cols + base);
        int4 cb = *(const int4*)(cols + base + 4);
        float4 va = *(const float4*)(vals + base);
        float4 vb = *(const float4*)(vals + base + 4);
        int p0 = atomicAdd(&cursor[ra.x], 1);
        int p1 = atomicAdd(&cursor[ra.y], 1);
        int p2 = atomicAdd(&cursor[ra.z], 1);
        int p3 = atomicAdd(&cursor[ra.w], 1);
        int p4 = atomicAdd(&cursor[rb.x], 1);
        int p5 = atomicAdd(&cursor[rb.y], 1);
        int p6 = atomicAdd(&cursor[rb.z], 1);
        int p7 = atomicAdd(&cursor[rb.w], 1);
        edges[p0] = make_float2(__int_as_float(ca.x + cbase), va.x);
        edges[p1] = make_float2(__int_as_float(ca.y + cbase), va.y);
        edges[p2] = make_float2(__int_as_float(ca.z + cbase), va.z);
        edges[p3] = make_float2(__int_as_float(ca.w + cbase), va.w);
        edges[p4] = make_float2(__int_as_float(cb.x + cbase), vb.x);
        edges[p5] = make_float2(__int_as_float(cb.y + cbase), vb.y);
        edges[p6] = make_float2(__int_as_float(cb.z + cbase), vb.z);
        edges[p7] = make_float2(__int_as_float(cb.w + cbase), vb.w);
    } else {
        for (int k = base; k < nnz; k++) {
            int pos = atomicAdd(&cursor[rows[k]], 1);
            edges[pos] = make_float2(__int_as_float(cols[k] + cbase), vals[k]);
        }
    }
}

// map global row -> output row pointer (fixed packing of the 6 tables)
__device__ __forceinline__ float* out_ptr(float* out, int row, int U, int NI, int NB,
                                          int R1, int R2) {
    size_t off;
    if (row < R1) {
        off = (row < U) ? (size_t)row : (size_t)(2 * U + 2 * NB) + (row - U);
    } else if (row < R2) {
        int l = row - R1;
        off = (l < NB) ? (size_t)(2 * U) + l : (size_t)(2 * U + 2 * NB + NI) + (l - NB);
    } else {
        int l = row - R2;
        off = (l < U) ? (size_t)U + l : (size_t)(2 * U + NB) + (l - U);
    }
    return out + off * D;
}

#define EPAD make_float2(__int_as_float(0), 0.0f)

// ---- fused gather-SpMM, software-pipelined (edges of batch k+1 load under
//      the gather latency of batch k; padded lanes gather row 0 with val 0) ----
template <bool FIRST>
__global__ void __launch_bounds__(128, 10)
spmm_kernel(const float2* __restrict__ edges, const int* __restrict__ offs,
            const __half* __restrict__ fin, __half* __restrict__ fnext,
            int ntot, int U, int NI, int NB, int R1, int R2,
            float* __restrict__ out) {
    int row = blockIdx.x * 4 + (threadIdx.x >> 5);
    if (row >= ntot) return;
    int lane = threadIdx.x & 31;
    int chunk = lane & 15;
    int half = lane >> 4;
    int s = __ldg(offs + row), e = __ldg(offs + row + 1);
    int mid = s + (((e - s) + 1) >> 1);
    int lo = half ? mid : s;
    int hi = half ? e : mid;

    float4 acc = make_float4(0.f, 0.f, 0.f, 0.f);
    int i = lo;
    if (i < hi) {
        float2 c0 = __ldg(edges + i);
        float2 c1 = (i + 1 < hi) ? __ldg(edges + i + 1) : EPAD;
        float2 c2 = (i + 2 < hi) ? __ldg(edges + i + 2) : EPAD;
        float2 c3 = (i + 3 < hi) ? __ldg(edges + i + 3) : EPAD;
        while (true) {
            uint2 r0 = *((const uint2*)(fin + (size_t)__float_as_int(c0.x) * D) + chunk);
            uint2 r1 = *((const uint2*)(fin + (size_t)__float_as_int(c1.x) * D) + chunk);
            uint2 r2 = *((const uint2*)(fin + (size_t)__float_as_int(c2.x) * D) + chunk);
            uint2 r3 = *((const uint2*)(fin + (size_t)__float_as_int(c3.x) * D) + chunk);
            i += 4;
            bool more = (i < hi);
            float2 n0, n1, n2, n3;
            if (more) {
                n0 = __ldg(edges + i);
                n1 = (i + 1 < hi) ? __ldg(edges + i + 1) : EPAD;
                n2 = (i + 2 < hi) ? __ldg(edges + i + 2) : EPAD;
                n3 = (i + 3 < hi) ? __ldg(edges + i + 3) : EPAD;
            }
            float2 a0 = __half22float2(*(__half2*)&r0.x), b0 = __half22float2(*(__half2*)&r0.y);
            float2 a1 = __half22float2(*(__half2*)&r1.x), b1 = __half22float2(*(__half2*)&r1.y);
            float2 a2 = __half22float2(*(__half2*)&r2.x), b2 = __half22float2(*(__half2*)&r2.y);
            float2 a3 = __half22float2(*(__half2*)&r3.x), b3 = __half22float2(*(__half2*)&r3.y);
            acc.x += c0.y * a0.x; acc.y += c0.y * a0.y; acc.z += c0.y * b0.x; acc.w += c0.y * b0.y;
            acc.x += c1.y * a1.x; acc.y += c1.y * a1.y; acc.z += c1.y * b1.x; acc.w += c1.y * b1.y;
            acc.x += c2.y * a2.x; acc.y += c2.y * a2.y; acc.z += c2.y * b2.x; acc.w += c2.y * b2.y;
            acc.x += c3.y * a3.x; acc.y += c3.y * a3.y; acc.z += c3.y * b3.x; acc.w += c3.y * b3.y;
            if (!more) break;
            c0 = n0; c1 = n1; c2 = n2; c3 = n3;
        }
    }
    float4 a = acc;
    a.x += __shfl_xor_sync(0xffffffffu, a.x, 16);
    a.y += __shfl_xor_sync(0xffffffffu, a.y, 16);
    a.z += __shfl_xor_sync(0xffffffffu, a.z, 16);
    a.w += __shfl_xor_sync(0xffffffffu, a.w, 16);
    float ss = a.x * a.x + a.y * a.y + a.z * a.z + a.w * a.w;
    #pragma unroll
    for (int o = 8; o; o >>= 1) ss += __shfl_xor_sync(0xffffffffu, ss, o);
    const float k = 1.0f / 3.0f;
    float scale = k / fmaxf(sqrtf(ss), 1e-12f);

    float* dst = out_ptr(out, row, U, NI, NB, R1, R2);
    if (FIRST) {
        if (half == 0) {
            __half2 h0 = __floats2half2_rn(a.x, a.y);
            __half2 h1 = __floats2half2_rn(a.z, a.w);
            uint2 packed;
            packed.x = *(const unsigned int*)&h0;
            packed.y = *(const unsigned int*)&h1;
            *((uint2*)(fnext + (size_t)row * D) + chunk) = packed;
        } else {
            uint2 r = *((const uint2*)(fin + (size_t)row * D) + chunk);
            float2 fa = __half22float2(*(__half2*)&r.x);
            float2 fb = __half22float2(*(__half2*)&r.y);
            *((float4*)dst + chunk) = make_float4(
                fa.x * k + a.x * scale, fa.y * k + a.y * scale,
                fb.x * k + a.z * scale, fb.y * k + a.w * scale);
        }
    } else {
        if (half == 0) {
            float4* d = (float4*)dst + chunk;
            float4 o = *d;
            o.x += a.x * scale; o.y += a.y * scale;
            o.z += a.z * scale; o.w += a.w * scale;
            *d = o;
        }
    }
}

// ---- persistent streams/events ----
static cudaStream_t s_strm[3];
static cudaEvent_t s_root, s_done[3];
static bool s_ready = false;

extern "C" void kernel_launch(void* const* d_in, const int* in_sizes, int n_in,
                              void* d_out, int out_size) {
    const float* users_feature   = (const float*)d_in[0];
    const float* items_feature   = (const float*)d_in[1];
    const float* bundles_feature = (const float*)d_in[2];
    const float* vals_[3] = {(const float*)d_in[3], (const float*)d_in[4], (const float*)d_in[5]};
    const int* rows_[3] = {(const int*)d_in[6], (const int*)d_in[8], (const int*)d_in[10]};
    const int* cols_[3] = {(const int*)d_in[7], (const int*)d_in[9], (const int*)d_in[11]};

    int U  = in_sizes[0] / D;
    int NI = in_sizes[1] / D;
    int NB = in_sizes[2] / D;
    int nnz_[3] = {in_sizes[3], in_sizes[4], in_sizes[5]};   // UI, BI, UB

    int R1 = U + NI;
    int R2 = R1 + NB + NI;
    int ntot = R2 + U + NB;

    if (!s_ready) {
        for (int g = 0; g < 3; g++) {
            cudaStreamCreateWithFlags(&s_strm[g], cudaStreamNonBlocking);
            cudaEventCreateWithFlags(&s_done[g], cudaEventDisableTiming);
        }
        cudaEventCreateWithFlags(&s_root, cudaEventDisableTiming);
        s_ready = true;
    }

    float* out = (float*)d_out;
    __half *f0, *f1;
    float2* edges;
    int *counts, *offs, *cursor;
    unsigned long long* desc;
    unsigned int* ticket;
    cudaGetSymbolAddress((void**)&f0, g_f0);
    cudaGetSymbolAddress((void**)&f1, g_f1);
    cudaGetSymbolAddress((void**)&edges, g_edges);
    cudaGetSymbolAddress((void**)&counts, g_counts);
    cudaGetSymbolAddress((void**)&offs, g_offs);
    cudaGetSymbolAddress((void**)&cursor, g_cursor);
    cudaGetSymbolAddress((void**)&desc, g_desc);
    cudaGetSymbolAddress((void**)&ticket, g_ticket);

    struct G { int rbase, n, ebase; };
    G gs[3] = {
        {0,  U + NI,  0},
        {R1, NB + NI, nnz_[0]},
        {R2, U + NB,  nnz_[0] + nnz_[1]},
    };

    // fork: per-graph CSR builds on 3 side streams; f0 init on main stream
    cudaEventRecord(s_root, 0);
    for (int g = 0; g < 3; g++) {
        cudaStream_t st = s_strm[g];
        const G& G_ = gs[g];
        int n = G_.n;
        int nb = (n + SCAN_B - 1) / SCAN_B;
        int* cnt = counts + G_.rbase;
        int* off = offs + G_.rbase;
        int* cur = cursor + G_.rbase;
        unsigned long long* dsc = desc + (size_t)g * MAXBLKS;
        unsigned int* tkt = ticket + g;

        cudaStreamWaitEvent(st, s_root, 0);
        cudaMemsetAsync(cnt, 0, (size_t)n * sizeof(int), st);
        cudaMemsetAsync(dsc, 0, (size_t)nb * sizeof(unsigned long long), st);
        cudaMemsetAsync(tkt, 0, sizeof(unsigned int), st);

        int eth = (nnz_[g] + 7) / 8;
        hist_kernel<<<(eth + 255) / 256, 256, 0, st>>>(rows_[g], nnz_[g], cnt);
        scan_kernel<<<nb, SCAN_B, 0, st>>>(cnt, n, G_.ebase, off, cur, dsc, tkt);
        bucket_kernel<<<(eth + 255) / 256, 256, 0, st>>>(rows_[g], cols_[g], vals_[g],
                                                         nnz_[g], G_.rbase, cur, edges);
        cudaEventRecord(s_done[g], st);
    }

    init_kernel<<<(ntot * (D / 4) + 255) / 256, 256>>>(
        users_feature, items_feature, bundles_feature, U, NB, R1, R2, ntot, f0);

    for (int g = 0; g < 3; g++)
        cudaStreamWaitEvent(0, s_done[g], 0);

    // merged spmm phases over all rows
    int blocks = (ntot + 3) / 4;
    spmm_kernel<true><<<blocks, 128>>>(edges, offs, f0, f1,
                                       ntot, U, NI, NB, R1, R2, out);
    spmm_kernel<false><<<blocks, 128>>>(edges, offs, f1, nullptr,
                                        ntot, U, NI, NB, R1, R2, out);
}

// round 9
// speedup vs baseline: 1.2983x; 1.2017x over previous
#include <cuda_runtime.h>
#include <cuda_fp16.h>
#include <cstdint>

#define D 64
#define MAXNTOT 340008
#define MAXNNZALL 4000008
#define SCAN_B 256
#define MAXBLKS ((150016 + SCAN_B - 1) / SCAN_B)

// ---- scratch (__device__ globals; no allocation allowed) ----
__device__ __align__(16) __half g_f0[(size_t)MAXNTOT * D];   // ~43.5 MB
__device__ __align__(16) __half g_f1[(size_t)MAXNTOT * D];   // ~43.5 MB
__device__ __align__(16) float2 g_edges[MAXNNZALL];          // {global col bits, val}
__device__ int g_counts[MAXNTOT];
__device__ int g_offs[MAXNTOT + 1];
__device__ int g_cursor[MAXNTOT];
__device__ unsigned long long g_desc[3][MAXBLKS];
__device__ unsigned int g_ticket[3];

// ---- init: f0(fp16) = concat of all three propagation inputs ----
__global__ void init_kernel(const float* __restrict__ Uf, const float* __restrict__ If,
                            const float* __restrict__ Bf,
                            int U, int NB, int R1, int R2, int ntot,
                            __half* __restrict__ f0) {
    int idx = blockIdx.x * blockDim.x + threadIdx.x;
    if (idx >= ntot * (D / 4)) return;
    int row = idx >> 4;
    int c = (idx & 15) * 4;
    const float* src;
    if (row < R1) {
        src = (row < U) ? (Uf + (size_t)row * D) : (If + (size_t)(row - U) * D);
    } else if (row < R2) {
        int l = row - R1;
        src = (l < NB) ? (Bf + (size_t)l * D) : (If + (size_t)(l - NB) * D);
    } else {
        int l = row - R2;
        src = (l < U) ? (Uf + (size_t)l * D) : (Bf + (size_t)(l - U) * D);
    }
    float4 v = *(const float4*)(src + c);
    __half2 h0 = __floats2half2_rn(v.x, v.y);
    __half2 h1 = __floats2half2_rn(v.z, v.w);
    uint2 packed;
    packed.x = *(const unsigned int*)&h0;
    packed.y = *(const unsigned int*)&h1;
    *(uint2*)(f0 + (size_t)row * D + c) = packed;
}

// ---- per-graph histogram (8 edges/thread) ----
__global__ void hist_kernel(const int* __restrict__ rows, int nnz, int* __restrict__ counts) {
    int base = (blockIdx.x * blockDim.x + threadIdx.x) * 8;
    if (base + 8 <= nnz) {
        int4 r0 = *(const int4*)(rows + base);
        int4 r1 = *(const int4*)(rows + base + 4);
        atomicAdd(&counts[r0.x], 1); atomicAdd(&counts[r0.y], 1);
        atomicAdd(&counts[r0.z], 1); atomicAdd(&counts[r0.w], 1);
        atomicAdd(&counts[r1.x], 1); atomicAdd(&counts[r1.y], 1);
        atomicAdd(&counts[r1.z], 1); atomicAdd(&counts[r1.w], 1);
    } else {
        for (int k = base; k < nnz; k++) atomicAdd(&counts[rows[k]], 1);
    }
}

// ---- per-graph decoupled-lookback scan; writes GLOBAL offsets (base = edge base) ----
__global__ void scan_kernel(const int* __restrict__ counts, int n, int base,
                            int* __restrict__ offs, int* __restrict__ cursor,
                            unsigned long long* __restrict__ desc,
                            unsigned int* __restrict__ ticket) {
    __shared__ int s_warp[8];
    __shared__ int s_bid;
    __shared__ int s_excl;
    int lane = threadIdx.x & 31;
    int wid = threadIdx.x >> 5;
    if (threadIdx.x == 0) s_bid = (int)atomicAdd(ticket, 1u);
    __syncthreads();
    int bid = s_bid;
    int i = bid * SCAN_B + threadIdx.x;
    int v = (i < n) ? counts[i] : 0;
    int x = v;
    #pragma unroll
    for (int o = 1; o < 32; o <<= 1) {
        int t = __shfl_up_sync(0xffffffffu, x, o);
        if (lane >= o) x += t;
    }
    if (lane == 31) s_warp[wid] = x;
    __syncthreads();
    if (wid == 0 && lane < 8) {
        int w = s_warp[lane];
        #pragma unroll
        for (int o = 1; o < 8; o <<= 1) {
            int t = __shfl_up_sync(0xffu, w, o);
            if (lane >= o) w += t;
        }
        s_warp[lane] = w;
    }
    __syncthreads();
    int incl = x + (wid ? s_warp[wid - 1] : 0);
    int total = s_warp[7];
    if (threadIdx.x == 0) {
        if (bid == 0) {
            atomicExch(&desc[0], (2ULL << 62) | (unsigned long long)(unsigned)total);
            s_excl = 0;
        } else {
            atomicExch(&desc[bid], (1ULL << 62) | (unsigned long long)(unsigned)total);
            int excl = 0;
            int j = bid - 1;
            while (true) {
                unsigned long long d;
                do { d = atomicAdd(&desc[j], 0ULL); } while ((d >> 62) == 0ULL);
                excl += (int)(unsigned)d;
                if ((d >> 62) == 2ULL) break;
                j--;
            }
            s_excl = excl;
            atomicExch(&desc[bid], (2ULL << 62) | (unsigned long long)(unsigned)(excl + total));
        }
    }
    __syncthreads();
    int excl = s_excl;
    if (i < n) {
        int inc = incl + excl + base;
        offs[i + 1] = inc;
        cursor[i] = inc - v;
        if (i == 0) offs[0] = base;
    }
}

// ---- per-graph bucket: edges -> (GLOBAL col = local + cbase, val) ----
__global__ void bucket_kernel(const int* __restrict__ rows, const int* __restrict__ cols,
                              const float* __restrict__ vals, int nnz, int cbase,
                              int* __restrict__ cursor, float2* __restrict__ edges) {
    int base = (blockIdx.x * blockDim.x + threadIdx.x) * 8;
    if (base + 8 <= nnz) {
        int4 ra = *(const int4*)(rows + base);
        int4 rb = *(const int4*)(rows + base + 4);
        int4 ca = *(const int4*)(cols + base);
        int4 cb = *(const int4*)(cols + base + 4);
        float4 va = *(const float4*)(vals + base);
        float4 vb = *(const float4*)(vals + base + 4);
        int p0 = atomicAdd(&cursor[ra.x], 1);
        int p1 = atomicAdd(&cursor[ra.y], 1);
        int p2 = atomicAdd(&cursor[ra.z], 1);
        int p3 = atomicAdd(&cursor[ra.w], 1);
        int p4 = atomicAdd(&cursor[rb.x], 1);
        int p5 = atomicAdd(&cursor[rb.y], 1);
        int p6 = atomicAdd(&cursor[rb.z], 1);
        int p7 = atomicAdd(&cursor[rb.w], 1);
        edges[p0] = make_float2(__int_as_float(ca.x + cbase), va.x);
        edges[p1] = make_float2(__int_as_float(ca.y + cbase), va.y);
        edges[p2] = make_float2(__int_as_float(ca.z + cbase), va.z);
        edges[p3] = make_float2(__int_as_float(ca.w + cbase), va.w);
        edges[p4] = make_float2(__int_as_float(cb.x + cbase), vb.x);
        edges[p5] = make_float2(__int_as_float(cb.y + cbase), vb.y);
        edges[p6] = make_float2(__int_as_float(cb.z + cbase), vb.z);
        edges[p7] = make_float2(__int_as_float(cb.w + cbase), vb.w);
    } else {
        for (int k = base; k < nnz; k++) {
            int pos = atomicAdd(&cursor[rows[k]], 1);
            edges[pos] = make_float2(__int_as_float(cols[k] + cbase), vals[k]);
        }
    }
}

// map global row -> output row pointer (fixed packing of the 6 tables)
__device__ __forceinline__ float* out_ptr(float* out, int row, int U, int NI, int NB,
                                          int R1, int R2) {
    size_t off;
    if (row < R1) {
        off = (row < U) ? (size_t)row : (size_t)(2 * U + 2 * NB) + (row - U);
    } else if (row < R2) {
        int l = row - R1;
        off = (l < NB) ? (size_t)(2 * U) + l : (size_t)(2 * U + 2 * NB + NI) + (l - NB);
    } else {
        int l = row - R2;
        off = (l < U) ? (size_t)U + l : (size_t)(2 * U + NB) + (l - U);
    }
    return out + off * D;
}

#define EPAD make_float2(__int_as_float(0), 0.0f)

// ---- fused gather-SpMM: ONE ROW PER 16-LANE HALF (2 independent rows/warp).
// Each half gathers the full 128B fp16 row (16 lanes x uint2), pipelined 4 deep;
// norm reduce within the half; per-half epilogue (fnext/out for its own row).
template <bool FIRST>
__global__ void __launch_bounds__(256)
spmm_kernel(const float2* __restrict__ edges, const int* __restrict__ offs,
            const __half* __restrict__ fin, __half* __restrict__ fnext,
            int ntot, int U, int NI, int NB, int R1, int R2,
            float* __restrict__ out) {
    int warp = blockIdx.x * (blockDim.x >> 5) + (threadIdx.x >> 5);
    int lane = threadIdx.x & 31;
    int half = lane >> 4;
    int chunk = lane & 15;
    int row = warp * 2 + half;            // ntot even -> warp fully in or out
    if (warp * 2 >= ntot) return;
    unsigned hmask = half ? 0xffff0000u : 0x0000ffffu;

    int lo = __ldg(offs + row), hi = __ldg(offs + row + 1);

    float4 acc = make_float4(0.f, 0.f, 0.f, 0.f);
    int i = lo;
    if (i < hi) {
        float2 c0 = __ldg(edges + i);
        float2 c1 = (i + 1 < hi) ? __ldg(edges + i + 1) : EPAD;
        float2 c2 = (i + 2 < hi) ? __ldg(edges + i + 2) : EPAD;
        float2 c3 = (i + 3 < hi) ? __ldg(edges + i + 3) : EPAD;
        while (true) {
            uint2 r0 = *((const uint2*)(fin + (size_t)__float_as_int(c0.x) * D) + chunk);
            uint2 r1 = *((const uint2*)(fin + (size_t)__float_as_int(c1.x) * D) + chunk);
            uint2 r2 = *((const uint2*)(fin + (size_t)__float_as_int(c2.x) * D) + chunk);
            uint2 r3 = *((const uint2*)(fin + (size_t)__float_as_int(c3.x) * D) + chunk);
            i += 4;
            bool more = (i < hi);
            float2 n0, n1, n2, n3;
            if (more) {
                n0 = __ldg(edges + i);
                n1 = (i + 1 < hi) ? __ldg(edges + i + 1) : EPAD;
                n2 = (i + 2 < hi) ? __ldg(edges + i + 2) : EPAD;
                n3 = (i + 3 < hi) ? __ldg(edges + i + 3) : EPAD;
            }
            float2 a0 = __half22float2(*(__half2*)&r0.x), b0 = __half22float2(*(__half2*)&r0.y);
            float2 a1 = __half22float2(*(__half2*)&r1.x), b1 = __half22float2(*(__half2*)&r1.y);
            float2 a2 = __half22float2(*(__half2*)&r2.x), b2 = __half22float2(*(__half2*)&r2.y);
            float2 a3 = __half22float2(*(__half2*)&r3.x), b3 = __half22float2(*(__half2*)&r3.y);
            acc.x += c0.y * a0.x; acc.y += c0.y * a0.y; acc.z += c0.y * b0.x; acc.w += c0.y * b0.y;
            acc.x += c1.y * a1.x; acc.y += c1.y * a1.y; acc.z += c1.y * b1.x; acc.w += c1.y * b1.y;
            acc.x += c2.y * a2.x; acc.y += c2.y * a2.y; acc.z += c2.y * b2.x; acc.w += c2.y * b2.y;
            acc.x += c3.y * a3.x; acc.y += c3.y * a3.y; acc.z += c3.y * b3.x; acc.w += c3.y * b3.y;
            if (!more) break;
            c0 = n0; c1 = n1; c2 = n2; c3 = n3;
        }
    }
    // norm reduce over the 16 lanes of this half only
    float ss = acc.x * acc.x + acc.y * acc.y + acc.z * acc.z + acc.w * acc.w;
    #pragma unroll
    for (int o = 8; o; o >>= 1) ss += __shfl_xor_sync(hmask, ss, o);
    const float k = 1.0f / 3.0f;
    float scale = k / fmaxf(sqrtf(ss), 1e-12f);

    float* dst = out_ptr(out, row, U, NI, NB, R1, R2);
    if (FIRST) {
        // write fnext (fp16) for layer 2
        __half2 h0 = __floats2half2_rn(acc.x, acc.y);
        __half2 h1 = __floats2half2_rn(acc.z, acc.w);
        uint2 packed;
        packed.x = *(const unsigned int*)&h0;
        packed.y = *(const unsigned int*)&h1;
        *((uint2*)(fnext + (size_t)row * D) + chunk) = packed;
        // out = own_feat/3 + norm(acc)/3
        uint2 r = *((const uint2*)(fin + (size_t)row * D) + chunk);
        float2 fa = __half22float2(*(__half2*)&r.x);
        float2 fb = __half22float2(*(__half2*)&r.y);
        *((float4*)dst + chunk) = make_float4(
            fa.x * k + acc.x * scale, fa.y * k + acc.y * scale,
            fb.x * k + acc.z * scale, fb.y * k + acc.w * scale);
    } else {
        float4* d = (float4*)dst + chunk;
        float4 o = *d;
        o.x += acc.x * scale; o.y += acc.y * scale;
        o.z += acc.z * scale; o.w += acc.w * scale;
        *d = o;
    }
}

// ---- persistent streams/events ----
static cudaStream_t s_strm[3];
static cudaEvent_t s_root, s_done[3];
static bool s_ready = false;

extern "C" void kernel_launch(void* const* d_in, const int* in_sizes, int n_in,
                              void* d_out, int out_size) {
    const float* users_feature   = (const float*)d_in[0];
    const float* items_feature   = (const float*)d_in[1];
    const float* bundles_feature = (const float*)d_in[2];
    const float* vals_[3] = {(const float*)d_in[3], (const float*)d_in[4], (const float*)d_in[5]};
    const int* rows_[3] = {(const int*)d_in[6], (const int*)d_in[8], (const int*)d_in[10]};
    const int* cols_[3] = {(const int*)d_in[7], (const int*)d_in[9], (const int*)d_in[11]};

    int U  = in_sizes[0] / D;
    int NI = in_sizes[1] / D;
    int NB = in_sizes[2] / D;
    int nnz_[3] = {in_sizes[3], in_sizes[4], in_sizes[5]};   // UI, BI, UB

    int R1 = U + NI;
    int R2 = R1 + NB + NI;
    int ntot = R2 + U + NB;

    if (!s_ready) {
        for (int g = 0; g < 3; g++) {
            cudaStreamCreateWithFlags(&s_strm[g], cudaStreamNonBlocking);
            cudaEventCreateWithFlags(&s_done[g], cudaEventDisableTiming);
        }
        cudaEventCreateWithFlags(&s_root, cudaEventDisableTiming);
        s_ready = true;
    }

    float* out = (float*)d_out;
    __half *f0, *f1;
    float2* edges;
    int *counts, *offs, *cursor;
    unsigned long long* desc;
    unsigned int* ticket;
    cudaGetSymbolAddress((void**)&f0, g_f0);
    cudaGetSymbolAddress((void**)&f1, g_f1);
    cudaGetSymbolAddress((void**)&edges, g_edges);
    cudaGetSymbolAddress((void**)&counts, g_counts);
    cudaGetSymbolAddress((void**)&offs, g_offs);
    cudaGetSymbolAddress((void**)&cursor, g_cursor);
    cudaGetSymbolAddress((void**)&desc, g_desc);
    cudaGetSymbolAddress((void**)&ticket, g_ticket);

    struct G { int rbase, n, ebase; };
    G gs[3] = {
        {0,  U + NI,  0},
        {R1, NB + NI, nnz_[0]},
        {R2, U + NB,  nnz_[0] + nnz_[1]},
    };

    // fork: per-graph CSR builds on 3 side streams; f0 init on main stream
    cudaEventRecord(s_root, 0);
    for (int g = 0; g < 3; g++) {
        cudaStream_t st = s_strm[g];
        const G& G_ = gs[g];
        int n = G_.n;
        int nb = (n + SCAN_B - 1) / SCAN_B;
        int* cnt = counts + G_.rbase;
        int* off = offs + G_.rbase;
        int* cur = cursor + G_.rbase;
        unsigned long long* dsc = desc + (size_t)g * MAXBLKS;
        unsigned int* tkt = ticket + g;

        cudaStreamWaitEvent(st, s_root, 0);
        cudaMemsetAsync(cnt, 0, (size_t)n * sizeof(int), st);
        cudaMemsetAsync(dsc, 0, (size_t)nb * sizeof(unsigned long long), st);
        cudaMemsetAsync(tkt, 0, sizeof(unsigned int), st);

        int eth = (nnz_[g] + 7) / 8;
        hist_kernel<<<(eth + 255) / 256, 256, 0, st>>>(rows_[g], nnz_[g], cnt);
        scan_kernel<<<nb, SCAN_B, 0, st>>>(cnt, n, G_.ebase, off, cur, dsc, tkt);
        bucket_kernel<<<(eth + 255) / 256, 256, 0, st>>>(rows_[g], cols_[g], vals_[g],
                                                         nnz_[g], G_.rbase, cur, edges);
        cudaEventRecord(s_done[g], st);
    }

    init_kernel<<<(ntot * (D / 4) + 255) / 256, 256>>>(
        users_feature, items_feature, bundles_feature, U, NB, R1, R2, ntot, f0);

    for (int g = 0; g < 3; g++)
        cudaStreamWaitEvent(0, s_done[g], 0);

    // merged spmm phases over all rows; 2 rows per warp, 16 rows per block
    int blocks = (ntot + 15) / 16;
    spmm_kernel<true><<<blocks, 256>>>(edges, offs, f0, f1,
                                       ntot, U, NI, NB, R1, R2, out);
    spmm_kernel<false><<<blocks, 256>>>(edges, offs, f1, nullptr,
                                        ntot, U, NI, NB, R1, R2, out);
}

// round 10
// speedup vs baseline: 1.5164x; 1.1680x over previous
#include <cuda_runtime.h>
#include <cuda_fp16.h>
#include <cstdint>

#define D 64
#define MAXNTOT 340008
#define MAXNNZALL 4000008
#define SCAN_B 256
#define MAXBLKS ((150016 + SCAN_B - 1) / SCAN_B)

// ---- scratch (__device__ globals; no allocation allowed) ----
__device__ __align__(16) __half g_f0[(size_t)MAXNTOT * D];   // ~43.5 MB
__device__ __align__(16) __half g_f1[(size_t)MAXNTOT * D];   // ~43.5 MB
__device__ __align__(16) float2 g_edges[MAXNNZALL];          // {global col bits, val}
__device__ int g_counts[MAXNTOT];
__device__ int g_offs[MAXNTOT + 1];
__device__ int g_cursor[MAXNTOT];
__device__ unsigned long long g_desc[3][MAXBLKS];
__device__ unsigned int g_ticket[3];

// ---- init: f0(fp16) = concat of all three propagation inputs ----
__global__ void init_kernel(const float* __restrict__ Uf, const float* __restrict__ If,
                            const float* __restrict__ Bf,
                            int U, int NB, int R1, int R2, int ntot,
                            __half* __restrict__ f0) {
    int idx = blockIdx.x * blockDim.x + threadIdx.x;
    if (idx >= ntot * (D / 4)) return;
    int row = idx >> 4;
    int c = (idx & 15) * 4;
    const float* src;
    if (row < R1) {
        src = (row < U) ? (Uf + (size_t)row * D) : (If + (size_t)(row - U) * D);
    } else if (row < R2) {
        int l = row - R1;
        src = (l < NB) ? (Bf + (size_t)l * D) : (If + (size_t)(l - NB) * D);
    } else {
        int l = row - R2;
        src = (l < U) ? (Uf + (size_t)l * D) : (Bf + (size_t)(l - U) * D);
    }
    float4 v = *(const float4*)(src + c);
    __half2 h0 = __floats2half2_rn(v.x, v.y);
    __half2 h1 = __floats2half2_rn(v.z, v.w);
    uint2 packed;
    packed.x = *(const unsigned int*)&h0;
    packed.y = *(const unsigned int*)&h1;
    *(uint2*)(f0 + (size_t)row * D + c) = packed;
}

// ---- per-graph histogram (4 edges/thread; more blocks -> more latency hiding) ----
__global__ void hist_kernel(const int* __restrict__ rows, int nnz, int* __restrict__ counts) {
    int base = (blockIdx.x * blockDim.x + threadIdx.x) * 4;
    if (base + 4 <= nnz) {
        int4 r = *(const int4*)(rows + base);
        atomicAdd(&counts[r.x], 1); atomicAdd(&counts[r.y], 1);
        atomicAdd(&counts[r.z], 1); atomicAdd(&counts[r.w], 1);
    } else {
        for (int k = base; k < nnz; k++) atomicAdd(&counts[rows[k]], 1);
    }
}

// ---- per-graph decoupled-lookback scan; writes GLOBAL offsets (base = edge base) ----
__global__ void scan_kernel(const int* __restrict__ counts, int n, int base,
                            int* __restrict__ offs, int* __restrict__ cursor,
                            unsigned long long* __restrict__ desc,
                            unsigned int* __restrict__ ticket) {
    __shared__ int s_warp[8];
    __shared__ int s_bid;
    __shared__ int s_excl;
    int lane = threadIdx.x & 31;
    int wid = threadIdx.x >> 5;
    if (threadIdx.x == 0) s_bid = (int)atomicAdd(ticket, 1u);
    __syncthreads();
    int bid = s_bid;
    int i = bid * SCAN_B + threadIdx.x;
    int v = (i < n) ? counts[i] : 0;
    int x = v;
    #pragma unroll
    for (int o = 1; o < 32; o <<= 1) {
        int t = __shfl_up_sync(0xffffffffu, x, o);
        if (lane >= o) x += t;
    }
    if (lane == 31) s_warp[wid] = x;
    __syncthreads();
    if (wid == 0 && lane < 8) {
        int w = s_warp[lane];
        #pragma unroll
        for (int o = 1; o < 8; o <<= 1) {
            int t = __shfl_up_sync(0xffu, w, o);
            if (lane >= o) w += t;
        }
        s_warp[lane] = w;
    }
    __syncthreads();
    int incl = x + (wid ? s_warp[wid - 1] : 0);
    int total = s_warp[7];
    if (threadIdx.x == 0) {
        if (bid == 0) {
            atomicExch(&desc[0], (2ULL << 62) | (unsigned long long)(unsigned)total);
            s_excl = 0;
        } else {
            atomicExch(&desc[bid], (1ULL << 62) | (unsigned long long)(unsigned)total);
            int excl = 0;
            int j = bid - 1;
            while (true) {
                unsigned long long d;
                do { d = atomicAdd(&desc[j], 0ULL); } while ((d >> 62) == 0ULL);
                excl += (int)(unsigned)d;
                if ((d >> 62) == 2ULL) break;
                j--;
            }
            s_excl = excl;
            atomicExch(&desc[bid], (2ULL << 62) | (unsigned long long)(unsigned)(excl + total));
        }
    }
    __syncthreads();
    int excl = s_excl;
    if (i < n) {
        int inc = incl + excl + base;
        offs[i + 1] = inc;
        cursor[i] = inc - v;
        if (i == 0) offs[0] = base;
    }
}

// ---- per-graph bucket: edges -> (GLOBAL col = local + cbase, val) ----
__global__ void bucket_kernel(const int* __restrict__ rows, const int* __restrict__ cols,
                              const float* __restrict__ vals, int nnz, int cbase,
                              int* __restrict__ cursor, float2* __restrict__ edges) {
    int base = (blockIdx.x * blockDim.x + threadIdx.x) * 4;
    if (base + 4 <= nnz) {
        int4 r = *(const int4*)(rows + base);
        int4 c = *(const int4*)(cols + base);
        float4 v = *(const float4*)(vals + base);
        int p0 = atomicAdd(&cursor[r.x], 1);
        int p1 = atomicAdd(&cursor[r.y], 1);
        int p2 = atomicAdd(&cursor[r.z], 1);
        int p3 = atomicAdd(&cursor[r.w], 1);
        edges[p0] = make_float2(__int_as_float(c.x + cbase), v.x);
        edges[p1] = make_float2(__int_as_float(c.y + cbase), v.y);
        edges[p2] = make_float2(__int_as_float(c.z + cbase), v.z);
        edges[p3] = make_float2(__int_as_float(c.w + cbase), v.w);
    } else {
        for (int k = base; k < nnz; k++) {
            int pos = atomicAdd(&cursor[rows[k]], 1);
            edges[pos] = make_float2(__int_as_float(cols[k] + cbase), vals[k]);
        }
    }
}

// map global row -> output row pointer (fixed packing of the 6 tables)
__device__ __forceinline__ float* out_ptr(float* out, int row, int U, int NI, int NB,
                                          int R1, int R2) {
    size_t off;
    if (row < R1) {
        off = (row < U) ? (size_t)row : (size_t)(2 * U + 2 * NB) + (row - U);
    } else if (row < R2) {
        int l = row - R1;
        off = (l < NB) ? (size_t)(2 * U) + l : (size_t)(2 * U + 2 * NB + NI) + (l - NB);
    } else {
        int l = row - R2;
        off = (l < U) ? (size_t)U + l : (size_t)(2 * U + NB) + (l - U);
    }
    return out + off * D;
}

#define EPAD make_float2(__int_as_float(0), 0.0f)

__device__ __forceinline__ void fma8(float* acc, float w, uint4 r) {
    float2 p0 = __half22float2(*(__half2*)&r.x);
    float2 p1 = __half22float2(*(__half2*)&r.y);
    float2 p2 = __half22float2(*(__half2*)&r.z);
    float2 p3 = __half22float2(*(__half2*)&r.w);
    acc[0] += w * p0.x; acc[1] += w * p0.y;
    acc[2] += w * p1.x; acc[3] += w * p1.y;
    acc[4] += w * p2.x; acc[5] += w * p2.y;
    acc[6] += w * p3.x; acc[7] += w * p3.y;
}

// ---- fused gather-SpMM: ONE ROW PER 8-LANE QUARTER (4 independent rows/warp).
// Lane gathers uint4 (16B of fp16) -> 8 lanes cover the 128B row in one LDG.128 each.
// 4-deep software pipeline per quarter => ~16 gathers + 16 edge loads in flight/warp.
template <bool FIRST>
__global__ void __launch_bounds__(256)
spmm_kernel(const float2* __restrict__ edges, const int* __restrict__ offs,
            const __half* __restrict__ fin, __half* __restrict__ fnext,
            int ntot, int U, int NI, int NB, int R1, int R2,
            float* __restrict__ out) {
    int warp = blockIdx.x * (blockDim.x >> 5) + (threadIdx.x >> 5);
    int lane = threadIdx.x & 31;
    int quarter = lane >> 3;
    int sub = lane & 7;
    int row = warp * 4 + quarter;
    if (row >= ntot) return;
    unsigned qmask = 0xffu << (quarter * 8);

    int lo = __ldg(offs + row), hi = __ldg(offs + row + 1);

    float acc[8] = {0.f, 0.f, 0.f, 0.f, 0.f, 0.f, 0.f, 0.f};
    int i = lo;
    if (i < hi) {
        float2 c0 = __ldg(edges + i);
        float2 c1 = (i + 1 < hi) ? __ldg(edges + i + 1) : EPAD;
        float2 c2 = (i + 2 < hi) ? __ldg(edges + i + 2) : EPAD;
        float2 c3 = (i + 3 < hi) ? __ldg(edges + i + 3) : EPAD;
        while (true) {
            uint4 r0 = *((const uint4*)(fin + (size_t)__float_as_int(c0.x) * D) + sub);
            uint4 r1 = *((const uint4*)(fin + (size_t)__float_as_int(c1.x) * D) + sub);
            uint4 r2 = *((const uint4*)(fin + (size_t)__float_as_int(c2.x) * D) + sub);
            uint4 r3 = *((const uint4*)(fin + (size_t)__float_as_int(c3.x) * D) + sub);
            i += 4;
            bool more = (i < hi);
            float2 n0, n1, n2, n3;
            if (more) {
                n0 = __ldg(edges + i);
                n1 = (i + 1 < hi) ? __ldg(edges + i + 1) : EPAD;
                n2 = (i + 2 < hi) ? __ldg(edges + i + 2) : EPAD;
                n3 = (i + 3 < hi) ? __ldg(edges + i + 3) : EPAD;
            }
            fma8(acc, c0.y, r0);
            fma8(acc, c1.y, r1);
            fma8(acc, c2.y, r2);
            fma8(acc, c3.y, r3);
            if (!more) break;
            c0 = n0; c1 = n1; c2 = n2; c3 = n3;
        }
    }
    // norm reduce over the 8 lanes of this quarter
    float ss = acc[0] * acc[0] + acc[1] * acc[1] + acc[2] * acc[2] + acc[3] * acc[3]
             + acc[4] * acc[4] + acc[5] * acc[5] + acc[6] * acc[6] + acc[7] * acc[7];
    #pragma unroll
    for (int o = 4; o; o >>= 1) ss += __shfl_xor_sync(qmask, ss, o);
    const float k = 1.0f / 3.0f;
    float scale = k / fmaxf(sqrtf(ss), 1e-12f);

    float* dst = out_ptr(out, row, U, NI, NB, R1, R2);
    if (FIRST) {
        // fnext (fp16) for layer 2
        __half2 h0 = __floats2half2_rn(acc[0], acc[1]);
        __half2 h1 = __floats2half2_rn(acc[2], acc[3]);
        __half2 h2 = __floats2half2_rn(acc[4], acc[5]);
        __half2 h3 = __floats2half2_rn(acc[6], acc[7]);
        uint4 packed;
        packed.x = *(const unsigned int*)&h0;
        packed.y = *(const unsigned int*)&h1;
        packed.z = *(const unsigned int*)&h2;
        packed.w = *(const unsigned int*)&h3;
        *((uint4*)(fnext + (size_t)row * D) + sub) = packed;
        // out = own_feat/3 + norm(acc)/3
        uint4 r = *((const uint4*)(fin + (size_t)row * D) + sub);
        float2 p0 = __half22float2(*(__half2*)&r.x);
        float2 p1 = __half22float2(*(__half2*)&r.y);
        float2 p2 = __half22float2(*(__half2*)&r.z);
        float2 p3 = __half22float2(*(__half2*)&r.w);
        float4* d = (float4*)dst + sub * 2;
        d[0] = make_float4(p0.x * k + acc[0] * scale, p0.y * k + acc[1] * scale,
                           p1.x * k + acc[2] * scale, p1.y * k + acc[3] * scale);
        d[1] = make_float4(p2.x * k + acc[4] * scale, p2.y * k + acc[5] * scale,
                           p3.x * k + acc[6] * scale, p3.y * k + acc[7] * scale);
    } else {
        float4* d = (float4*)dst + sub * 2;
        float4 o0 = d[0], o1 = d[1];
        o0.x += acc[0] * scale; o0.y += acc[1] * scale;
        o0.z += acc[2] * scale; o0.w += acc[3] * scale;
        o1.x += acc[4] * scale; o1.y += acc[5] * scale;
        o1.z += acc[6] * scale; o1.w += acc[7] * scale;
        d[0] = o0; d[1] = o1;
    }
}

// ---- persistent streams/events ----
static cudaStream_t s_strm[3];
static cudaEvent_t s_root, s_done[3];
static bool s_ready = false;

extern "C" void kernel_launch(void* const* d_in, const int* in_sizes, int n_in,
                              void* d_out, int out_size) {
    const float* users_feature   = (const float*)d_in[0];
    const float* items_feature   = (const float*)d_in[1];
    const float* bundles_feature = (const float*)d_in[2];
    const float* vals_[3] = {(const float*)d_in[3], (const float*)d_in[4], (const float*)d_in[5]};
    const int* rows_[3] = {(const int*)d_in[6], (const int*)d_in[8], (const int*)d_in[10]};
    const int* cols_[3] = {(const int*)d_in[7], (const int*)d_in[9], (const int*)d_in[11]};

    int U  = in_sizes[0] / D;
    int NI = in_sizes[1] / D;
    int NB = in_sizes[2] / D;
    int nnz_[3] = {in_sizes[3], in_sizes[4], in_sizes[5]};   // UI, BI, UB

    int R1 = U + NI;
    int R2 = R1 + NB + NI;
    int ntot = R2 + U + NB;

    if (!s_ready) {
        for (int g = 0; g < 3; g++) {
            cudaStreamCreateWithFlags(&s_strm[g], cudaStreamNonBlocking);
            cudaEventCreateWithFlags(&s_done[g], cudaEventDisableTiming);
        }
        cudaEventCreateWithFlags(&s_root, cudaEventDisableTiming);
        s_ready = true;
    }

    float* out = (float*)d_out;
    __half *f0, *f1;
    float2* edges;
    int *counts, *offs, *cursor;
    unsigned long long* desc;
    unsigned int* ticket;
    cudaGetSymbolAddress((void**)&f0, g_f0);
    cudaGetSymbolAddress((void**)&f1, g_f1);
    cudaGetSymbolAddress((void**)&edges, g_edges);
    cudaGetSymbolAddress((void**)&counts, g_counts);
    cudaGetSymbolAddress((void**)&offs, g_offs);
    cudaGetSymbolAddress((void**)&cursor, g_cursor);
    cudaGetSymbolAddress((void**)&desc, g_desc);
    cudaGetSymbolAddress((void**)&ticket, g_ticket);

    struct G { int rbase, n, ebase; };
    G gs[3] = {
        {0,  U + NI,  0},
        {R1, NB + NI, nnz_[0]},
        {R2, U + NB,  nnz_[0] + nnz_[1]},
    };

    // fork: per-graph CSR builds on 3 side streams; f0 init on main stream
    cudaEventRecord(s_root, 0);
    for (int g = 0; g < 3; g++) {
        cudaStream_t st = s_strm[g];
        const G& G_ = gs[g];
        int n = G_.n;
        int nb = (n + SCAN_B - 1) / SCAN_B;
        int* cnt = counts + G_.rbase;
        int* off = offs + G_.rbase;
        int* cur = cursor + G_.rbase;
        unsigned long long* dsc = desc + (size_t)g * MAXBLKS;
        unsigned int* tkt = ticket + g;

        cudaStreamWaitEvent(st, s_root, 0);
        cudaMemsetAsync(cnt, 0, (size_t)n * sizeof(int), st);
        cudaMemsetAsync(dsc, 0, (size_t)nb * sizeof(unsigned long long), st);
        cudaMemsetAsync(tkt, 0, sizeof(unsigned int), st);

        int eth = (nnz_[g] + 3) / 4;
        hist_kernel<<<(eth + 255) / 256, 256, 0, st>>>(rows_[g], nnz_[g], cnt);
        scan_kernel<<<nb, SCAN_B, 0, st>>>(cnt, n, G_.ebase, off, cur, dsc, tkt);
        bucket_kernel<<<(eth + 255) / 256, 256, 0, st>>>(rows_[g], cols_[g], vals_[g],
                                                         nnz_[g], G_.rbase, cur, edges);
        cudaEventRecord(s_done[g], st);
    }

    init_kernel<<<(ntot * (D / 4) + 255) / 256, 256>>>(
        users_feature, items_feature, bundles_feature, U, NB, R1, R2, ntot, f0);

    for (int g = 0; g < 3; g++)
        cudaStreamWaitEvent(0, s_done[g], 0);

    // merged spmm phases; 4 rows per warp, 32 rows per block
    int blocks = (ntot + 31) / 32;
    spmm_kernel<true><<<blocks, 256>>>(edges, offs, f0, f1,
                                       ntot, U, NI, NB, R1, R2, out);
    spmm_kernel<false><<<blocks, 256>>>(edges, offs, f1, nullptr,
                                        ntot, U, NI, NB, R1, R2, out);
}